// round 11
// baseline (speedup 1.0000x reference)
#include <cuda_runtime.h>

// YOLO loss, sm_103a — round 9: lean hybrid, 8 slices/image for latency hiding.
//   target-side (50 thr, slice 3): coord+cls gathers: 5·Σd² + 1 − 2·p_cls
//   stream (169 thr/slice, 8 slices): class ch  n·Σ_c p_c²  (fixed j, unroll 10)
//                                     conf ch   0.5·conf²   (conf0 masked n==0)

#define S_GRID   26
#define NCH      255
#define CELLS    676
#define Q4       169               // CELLS/4
#define BATCH_N  128
#define T_TGT    50
#define L_COORD  5.0f
#define L_NOOBJ  0.5f

#define CSPLIT   8                 // class-channel slices per image (10 ch each)
#define TPB      192
#define NBLOCKS  (BATCH_N * CSPLIT)    // 1024

__device__ float    g_acc = 0.0f;      // reset by last block each call
__device__ unsigned g_cnt = 0u;

__global__ __launch_bounds__(TPB)
void yolo_loss_kernel(const float* __restrict__ pred,
                      const float* __restrict__ tgt,
                      float* __restrict__ out)
{
    const int tid = threadIdx.x;
    const int b   = blockIdx.x >> 3;       // image
    const int r   = blockIdx.x & 7;        // slice (0..7)

    __shared__ float s_n[CELLS];
    __shared__ float s_warp[TPB / 32];

    // ---- phase A: per-cell valid-target count (n) ----
    for (int i = tid; i < CELLS; i += TPB) s_n[i] = 0.0f;
    __syncthreads();
    const float* tgb = tgt + (size_t)b * T_TGT * 5;
    if (tid < T_TGT) {
        const float cx = __ldg(tgb + tid * 5 + 1);
        const float cy = __ldg(tgb + tid * 5 + 2);
        const int gx = (int)(cx * S_GRID);      // trunc == floor (cx >= 0)
        const int gy = (int)(cy * S_GRID);
        if (gx < S_GRID && gy < S_GRID) {
            const int cell = min(max(gy,0),S_GRID-1) * S_GRID
                           + min(max(gx,0),S_GRID-1);
            atomicAdd(&s_n[cell], 1.0f);
        }
    }
    __syncthreads();

    float sum = 0.0f;
    const float* pb = pred + (size_t)b * NCH * CELLS;

    if (tid < Q4) {
        const int j = tid;                      // this thread's float4 column
        // ---- class-channel stream: 10 channels, fixed j ----
        const float4* base = (const float4*)(pb + (size_t)(5 + 10 * r) * CELLS) + j;
        float4 s = make_float4(0.f, 0.f, 0.f, 0.f);
        #pragma unroll
        for (int k = 0; k < 10; k++) {
            const float4 p = __ldg(base + k * Q4);
            s.x = fmaf(p.x, p.x, s.x);
            s.y = fmaf(p.y, p.y, s.y);
            s.z = fmaf(p.z, p.z, s.z);
            s.w = fmaf(p.w, p.w, s.w);
        }
        const float4 nv = *(const float4*)&s_n[4 * j];
        sum = nv.x * s.x + nv.y * s.y + nv.z * s.z + nv.w * s.w;

        // ---- conf channel duty (slices 0..2) ----
        if (r == 0) {                           // conf0, masked by n==0
            const float4 p = __ldg((const float4*)pb + j);
            float t = 0.f;
            t += (nv.x == 0.f) ? p.x * p.x : 0.f;
            t += (nv.y == 0.f) ? p.y * p.y : 0.f;
            t += (nv.z == 0.f) ? p.z * p.z : 0.f;
            t += (nv.w == 0.f) ? p.w * p.w : 0.f;
            sum += L_NOOBJ * t;
        } else if (r == 1) {                    // conf of box 1 (ch 85)
            const float4 p = __ldg((const float4*)(pb + (size_t)85 * CELLS) + j);
            sum += L_NOOBJ * (p.x*p.x + p.y*p.y + p.z*p.z + p.w*p.w);
        } else if (r == 2) {                    // conf of box 2 (ch 170)
            const float4 p = __ldg((const float4*)(pb + (size_t)170 * CELLS) + j);
            sum += L_NOOBJ * (p.x*p.x + p.y*p.y + p.z*p.z + p.w*p.w);
        }
    }

    // ---- target-side term (slice 3): coord + cls gather ----
    if (r == 3 && tid < T_TGT) {
        const float clsf = __ldg(tgb + tid * 5 + 0);
        const float cx   = __ldg(tgb + tid * 5 + 1);
        const float cy   = __ldg(tgb + tid * 5 + 2);
        const float tw   = __ldg(tgb + tid * 5 + 3);
        const float th   = __ldg(tgb + tid * 5 + 4);
        const int gx = (int)(cx * S_GRID);
        const int gy = (int)(cy * S_GRID);
        if (gx < S_GRID && gy < S_GRID) {
            const int cell = min(max(gy,0),S_GRID-1) * S_GRID
                           + min(max(gx,0),S_GRID-1);
            const float* cp = pb + cell;
            const int clsi = (int)clsf;
            const float p1 = __ldg(cp + (size_t)1 * CELLS);
            const float p2 = __ldg(cp + (size_t)2 * CELLS);
            const float p3 = __ldg(cp + (size_t)3 * CELLS);
            const float p4 = __ldg(cp + (size_t)4 * CELLS);
            const float pg = __ldg(cp + (size_t)(5 + clsi) * CELLS);
            const float d1 = p1 - cx, d2 = p2 - cy, d3 = p3 - tw, d4 = p4 - th;
            sum += L_COORD * (d1*d1 + d2*d2 + d3*d3 + d4*d4) + 1.0f - 2.0f * pg;
        }
    }

    // ---- block reduce + last-block-done finalization (single launch) ----
    const int lane = tid & 31;
    const int warp = tid >> 5;
    #pragma unroll
    for (int off = 16; off; off >>= 1)
        sum += __shfl_down_sync(0xffffffffu, sum, off);
    if (lane == 0) s_warp[warp] = sum;
    __syncthreads();
    if (tid == 0) {
        float v = s_warp[0];
        #pragma unroll
        for (int w = 1; w < TPB / 32; w++) v += s_warp[w];
        atomicAdd(&g_acc, v);
        __threadfence();
        const unsigned ticket = atomicAdd(&g_cnt, 1u);
        if (ticket == NBLOCKS - 1) {
            const float total = atomicAdd(&g_acc, 0.0f);   // coherent read
            out[0] = total * (1.0f / BATCH_N);
            g_acc = 0.0f;                                  // replay-safe reset
            g_cnt = 0u;
        }
    }
}

extern "C" void kernel_launch(void* const* d_in, const int* in_sizes, int n_in,
                              void* d_out, int out_size)
{
    const float* pred = (const float*)d_in[0];
    const float* tgt  = (const float*)d_in[1];
    float* out = (float*)d_out;

    yolo_loss_kernel<<<NBLOCKS, TPB>>>(pred, tgt, out);
}

// round 12
// speedup vs baseline: 1.2647x; 1.2647x over previous
#include <cuda_runtime.h>

// YOLO loss, sm_103a — round 11: R7 structure + load/prologue overlap.
// Stream LDGs + conf/target gathers are issued BEFORE the shared-memory
// phase-A (zero/scatter/barriers), hiding the prologue latency entirely.

#define S_GRID   26
#define NCH      255
#define CELLS    676
#define Q4       169               // CELLS/4
#define BATCH_N  128
#define T_TGT    50
#define L_COORD  5.0f
#define L_NOOBJ  0.5f

#define CSPLIT   4                 // class-channel slices per image (20 ch each)
#define TPB      192
#define NBLOCKS  (BATCH_N * CSPLIT)    // 512

__device__ float    g_acc = 0.0f;      // reset by last block each call
__device__ unsigned g_cnt = 0u;

__global__ __launch_bounds__(TPB)
void yolo_loss_kernel(const float* __restrict__ pred,
                      const float* __restrict__ tgt,
                      float* __restrict__ out)
{
    const int tid = threadIdx.x;
    const int b   = blockIdx.x >> 2;       // image
    const int r   = blockIdx.x & 3;        // slice (0..3)

    __shared__ float s_n[CELLS];
    __shared__ float s_warp[TPB / 32];

    const float* pb  = pred + (size_t)b * NCH * CELLS;
    const float* tgb = tgt  + (size_t)b * T_TGT * 5;

    float sum = 0.0f;

    // ================= EARLY ISSUE: all global loads, no smem deps =========
    // class-channel stream: 20 channels, fixed j, accumulate Σp² (n applied later)
    float4 s = make_float4(0.f, 0.f, 0.f, 0.f);
    float4 cp0 = make_float4(0.f, 0.f, 0.f, 0.f);   // conf0 (r==0), nv-masked later
    if (tid < Q4) {
        const int j = tid;
        const float4* base = (const float4*)(pb + (size_t)(5 + 20 * r) * CELLS) + j;
        #pragma unroll
        for (int k = 0; k < 20; k++) {
            const float4 p = __ldg(base + k * Q4);
            s.x = fmaf(p.x, p.x, s.x);
            s.y = fmaf(p.y, p.y, s.y);
            s.z = fmaf(p.z, p.z, s.z);
            s.w = fmaf(p.w, p.w, s.w);
        }
        if (r == 0) {
            cp0 = __ldg((const float4*)pb + j);
        } else if (r == 1) {                    // conf box 1 (ch 85): no mask
            const float4 p = __ldg((const float4*)(pb + (size_t)85 * CELLS) + j);
            sum += L_NOOBJ * (p.x*p.x + p.y*p.y + p.z*p.z + p.w*p.w);
        } else if (r == 2) {                    // conf box 2 (ch 170): no mask
            const float4 p = __ldg((const float4*)(pb + (size_t)170 * CELLS) + j);
            sum += L_NOOBJ * (p.x*p.x + p.y*p.y + p.z*p.z + p.w*p.w);
        }
    }

    // target data for this thread (used by phase A scatter and slice-3 gather)
    float clsf = 0.f, cx = 2.f, cy = 2.f, tw = 0.f, th = 0.f;   // cx=2 -> invalid
    if (tid < T_TGT) {
        clsf = __ldg(tgb + tid * 5 + 0);
        cx   = __ldg(tgb + tid * 5 + 1);
        cy   = __ldg(tgb + tid * 5 + 2);
        tw   = __ldg(tgb + tid * 5 + 3);
        th   = __ldg(tgb + tid * 5 + 4);
    }
    const int gx = (int)(cx * S_GRID);          // trunc == floor (cx >= 0)
    const int gy = (int)(cy * S_GRID);
    const bool tvalid = (tid < T_TGT) && (gx < S_GRID) && (gy < S_GRID);
    const int cell = min(max(gy,0),S_GRID-1) * S_GRID + min(max(gx,0),S_GRID-1);

    // slice-3 target-side gather: coord + class channels at this target's cell
    if (r == 3 && tvalid) {
        const float* cpp = pb + cell;
        const int clsi = (int)clsf;
        const float p1 = __ldg(cpp + (size_t)1 * CELLS);
        const float p2 = __ldg(cpp + (size_t)2 * CELLS);
        const float p3 = __ldg(cpp + (size_t)3 * CELLS);
        const float p4 = __ldg(cpp + (size_t)4 * CELLS);
        const float pg = __ldg(cpp + (size_t)(5 + clsi) * CELLS);
        const float d1 = p1 - cx, d2 = p2 - cy, d3 = p3 - tw, d4 = p4 - th;
        sum += L_COORD * (d1*d1 + d2*d2 + d3*d3 + d4*d4) + 1.0f - 2.0f * pg;
    }

    // ================= PHASE A: per-cell count n (overlapped w/ loads) ======
    for (int i = tid; i < CELLS; i += TPB) s_n[i] = 0.0f;
    __syncthreads();
    if (tvalid) atomicAdd(&s_n[cell], 1.0f);
    __syncthreads();

    // ================= COMBINE: apply n to the streamed sums ================
    if (tid < Q4) {
        const float4 nv = *(const float4*)&s_n[4 * tid];
        sum += nv.x * s.x + nv.y * s.y + nv.z * s.z + nv.w * s.w;
        if (r == 0) {
            float t = 0.f;
            t += (nv.x == 0.f) ? cp0.x * cp0.x : 0.f;
            t += (nv.y == 0.f) ? cp0.y * cp0.y : 0.f;
            t += (nv.z == 0.f) ? cp0.z * cp0.z : 0.f;
            t += (nv.w == 0.f) ? cp0.w * cp0.w : 0.f;
            sum += L_NOOBJ * t;
        }
    }

    // ---- block reduce + last-block-done finalization (single launch) ----
    const int lane = tid & 31;
    const int warp = tid >> 5;
    #pragma unroll
    for (int off = 16; off; off >>= 1)
        sum += __shfl_down_sync(0xffffffffu, sum, off);
    if (lane == 0) s_warp[warp] = sum;
    __syncthreads();
    if (tid == 0) {
        float v = s_warp[0];
        #pragma unroll
        for (int w = 1; w < TPB / 32; w++) v += s_warp[w];
        atomicAdd(&g_acc, v);
        __threadfence();
        const unsigned ticket = atomicAdd(&g_cnt, 1u);
        if (ticket == NBLOCKS - 1) {
            const float total = atomicAdd(&g_acc, 0.0f);   // coherent read
            out[0] = total * (1.0f / BATCH_N);
            g_acc = 0.0f;                                  // replay-safe reset
            g_cnt = 0u;
        }
    }
}

extern "C" void kernel_launch(void* const* d_in, const int* in_sizes, int n_in,
                              void* d_out, int out_size)
{
    const float* pred = (const float*)d_in[0];
    const float* tgt  = (const float*)d_in[1];
    float* out = (float*)d_out;

    yolo_loss_kernel<<<NBLOCKS, TPB>>>(pred, tgt, out);
}